// round 1
// baseline (speedup 1.0000x reference)
#include <cuda_runtime.h>

// SinkhornM: per-row MLP (8->32->16->9) -> tau (exp/sqrt 3x3) -> sigmoid shares
// -> 10-iter Sinkhorn-Knopp on 3x3 -> assemble 4x4 mus + V.
// Two rows per thread; all float math packed via Blackwell f32x2 instructions.

typedef unsigned long long F2;

static __device__ __forceinline__ float f2lo(F2 v){ return __uint_as_float((unsigned)v); }
static __device__ __forceinline__ float f2hi(F2 v){ return __uint_as_float((unsigned)(v >> 32)); }
static __device__ __forceinline__ F2 mkf2(float lo, float hi){
    return (F2)__float_as_uint(lo) | ((F2)__float_as_uint(hi) << 32);
}
static __device__ __forceinline__ F2 bb(float v){ return mkf2(v, v); }

static __device__ __forceinline__ F2 fma2(F2 a, F2 b, F2 c){
    F2 d; asm("fma.rn.f32x2 %0, %1, %2, %3;" : "=l"(d) : "l"(a), "l"(b), "l"(c)); return d;
}
static __device__ __forceinline__ F2 mul2(F2 a, F2 b){
    F2 d; asm("mul.rn.f32x2 %0, %1, %2;" : "=l"(d) : "l"(a), "l"(b)); return d;
}
static __device__ __forceinline__ F2 add2(F2 a, F2 b){
    F2 d; asm("add.rn.f32x2 %0, %1, %2;" : "=l"(d) : "l"(a), "l"(b)); return d;
}
static __device__ __forceinline__ float rcpa(float x){ float r; asm("rcp.approx.ftz.f32 %0, %1;" : "=f"(r) : "f"(x)); return r; }
static __device__ __forceinline__ float sqrta(float x){ float r; asm("sqrt.approx.ftz.f32 %0, %1;" : "=f"(r) : "f"(x)); return r; }
static __device__ __forceinline__ float ex2a(float x){ float r; asm("ex2.approx.ftz.f32 %0, %1;" : "=f"(r) : "f"(x)); return r; }

static __device__ __forceinline__ F2 rcp2(F2 v){ return mkf2(rcpa(f2lo(v)), rcpa(f2hi(v))); }
static __device__ __forceinline__ F2 sqrt2(F2 v){ return mkf2(sqrta(f2lo(v)), sqrta(f2hi(v))); }
static __device__ __forceinline__ F2 ex2_2(F2 v){ return mkf2(ex2a(f2lo(v)), ex2a(f2hi(v))); }
static __device__ __forceinline__ F2 expn2(F2 v){ return ex2_2(mul2(v, bb(1.4426950408889634f))); }
static __device__ __forceinline__ F2 relu2(F2 v){ return mkf2(fmaxf(f2lo(v), 0.f), fmaxf(f2hi(v), 0.f)); }

__global__ __launch_bounds__(128, 3)
void sinkhornm_kernel(const float* __restrict__ margins,
                      const float* __restrict__ W1, const float* __restrict__ b1,
                      const float* __restrict__ W2, const float* __restrict__ b2,
                      const float* __restrict__ W3, const float* __restrict__ b3,
                      float* __restrict__ out, int Btot, long long outsz)
{
    // Weights duplicated (w,w) into u64 so LDS.64/128 feeds fma.rn.f32x2 directly.
    __shared__ __align__(16) F2 sW1[256];
    __shared__ __align__(16) F2 sB1[32];
    __shared__ __align__(16) F2 sW2[512];
    __shared__ __align__(16) F2 sB2[16];
    __shared__ __align__(16) F2 sW3[160];   // 16 rows x stride 10 (9 used)
    __shared__ __align__(16) F2 sB3[16];

    const int tid = threadIdx.x;
    for (int i = tid; i < 256; i += blockDim.x) sW1[i] = bb(W1[i]);
    for (int i = tid; i < 32;  i += blockDim.x) sB1[i] = bb(b1[i]);
    for (int i = tid; i < 512; i += blockDim.x) sW2[i] = bb(W2[i]);
    for (int i = tid; i < 16;  i += blockDim.x) sB2[i] = bb(b2[i]);
    for (int i = tid; i < 144; i += blockDim.x) sW3[(i / 9) * 10 + (i % 9)] = bb(W3[i]);
    for (int i = tid; i < 9;   i += blockDim.x) sB3[i] = bb(b3[i]);
    __syncthreads();

    const long long t  = (long long)blockIdx.x * blockDim.x + tid;
    const long long r0 = 2 * t;
    if (r0 >= Btot) return;
    const bool hasHi = (r0 + 1) < Btot;
    const long long r1 = hasHi ? (r0 + 1) : r0;

    // Load margins for the two rows, pack lane-wise (lo = row r0, hi = row r1).
    const float4* mga = (const float4*)(margins + r0 * 8);
    const float4* mgb = (const float4*)(margins + r1 * 8);
    const float4 a0 = mga[0], a1 = mga[1];
    const float4 q0 = mgb[0], q1 = mgb[1];

    F2 mm[8];
    mm[0] = mkf2(a0.x, q0.x); mm[1] = mkf2(a0.y, q0.y);
    mm[2] = mkf2(a0.z, q0.z); mm[3] = mkf2(a0.w, q0.w);
    mm[4] = mkf2(a1.x, q1.x); mm[5] = mkf2(a1.y, q1.y);
    mm[6] = mkf2(a1.z, q1.z); mm[7] = mkf2(a1.w, q1.w);

    // ---- Layer 1: 8 -> 32, relu ----
    F2 h[32];
    {
        const ulonglong2* bv = (const ulonglong2*)sB1;
        #pragma unroll
        for (int j = 0; j < 16; j++){ ulonglong2 v = bv[j]; h[2*j] = v.x; h[2*j+1] = v.y; }
        const ulonglong2* wv = (const ulonglong2*)sW1;
        #pragma unroll
        for (int i = 0; i < 8; i++){
            const F2 x = mm[i];
            #pragma unroll
            for (int j = 0; j < 16; j++){
                ulonglong2 w = wv[i*16 + j];
                h[2*j]   = fma2(x, w.x, h[2*j]);
                h[2*j+1] = fma2(x, w.y, h[2*j+1]);
            }
        }
        #pragma unroll
        for (int j = 0; j < 32; j++) h[j] = relu2(h[j]);
    }

    // ---- Layer 2: 32 -> 16, relu ----
    F2 g[16];
    {
        const ulonglong2* bv = (const ulonglong2*)sB2;
        #pragma unroll
        for (int j = 0; j < 8; j++){ ulonglong2 v = bv[j]; g[2*j] = v.x; g[2*j+1] = v.y; }
        const ulonglong2* wv = (const ulonglong2*)sW2;
        #pragma unroll
        for (int i = 0; i < 32; i++){
            const F2 x = h[i];
            #pragma unroll
            for (int j = 0; j < 8; j++){
                ulonglong2 w = wv[i*8 + j];
                g[2*j]   = fma2(x, w.x, g[2*j]);
                g[2*j+1] = fma2(x, w.y, g[2*j+1]);
            }
        }
        #pragma unroll
        for (int j = 0; j < 16; j++) g[j] = relu2(g[j]);
    }

    // ---- Layer 3: 16 -> 9 ----
    F2 p[9];
    #pragma unroll
    for (int j = 0; j < 9; j++) p[j] = sB3[j];
    #pragma unroll
    for (int i = 0; i < 16; i++){
        const F2 x = g[i];
        const ulonglong2* row = (const ulonglong2*)(sW3 + i*10);
        ulonglong2 w01 = row[0], w23 = row[1], w45 = row[2], w67 = row[3];
        p[0] = fma2(x, w01.x, p[0]); p[1] = fma2(x, w01.y, p[1]);
        p[2] = fma2(x, w23.x, p[2]); p[3] = fma2(x, w23.y, p[3]);
        p[4] = fma2(x, w45.x, p[4]); p[5] = fma2(x, w45.y, p[5]);
        p[6] = fma2(x, w67.x, p[6]); p[7] = fma2(x, w67.y, p[7]);
        p[8] = fma2(x, sW3[i*10 + 8], p[8]);
    }

    // ---- tau: 3x3 matrix of exp / geometric means ----
    F2 e0 = expn2(p[0]), e1 = expn2(p[1]), e2 = expn2(p[2]), e3 = expn2(p[3]);
    F2 A[9];
    A[0] = e0; A[1] = e1; A[2] = sqrt2(mul2(e0, e1));
    A[3] = e2; A[4] = e3; A[5] = sqrt2(mul2(e2, e3));
    A[6] = sqrt2(mul2(e0, e2)); A[7] = sqrt2(mul2(e1, e3));
    A[8] = sqrt2(mul2(A[6], A[7]));

    // ---- sqs(x) = 0.02 + 0.96 * sigmoid(x) ----
    const F2 NL2E = bb(-1.4426950408889634f);
    const F2 ONE  = bb(1.0f);
    const F2 C96  = bb(0.96f);
    const F2 C02  = bb(0.02f);
    F2 sm0 = fma2(rcp2(add2(ex2_2(mul2(p[4], NL2E)), ONE)), C96, C02);
    F2 sm1 = fma2(rcp2(add2(ex2_2(mul2(p[5], NL2E)), ONE)), C96, C02);
    F2 sf0 = fma2(rcp2(add2(ex2_2(mul2(p[6], NL2E)), ONE)), C96, C02);
    F2 sf1 = fma2(rcp2(add2(ex2_2(mul2(p[7], NL2E)), ONE)), C96, C02);
    F2 Vv  = expn2(p[8]);

    // Row margins r = M * [sm0, sm1, 1]; col margins c = F * [sf0, sf1, 1]
    F2 rr[3] = { mul2(mm[0], sm0), mul2(mm[1], sm1), mm[2] };
    F2 cc[3] = { mul2(mm[3], sf0), mul2(mm[4], sf1), mm[5] };

    // ---- Sinkhorn-Knopp, 10 iterations ----
    const F2 EPS2 = bb(1e-12f);
    #pragma unroll 1
    for (int it = 0; it < 10; it++){
        #pragma unroll
        for (int k = 0; k < 3; k++){
            F2 s  = add2(add2(A[3*k], A[3*k+1]), A[3*k+2]);
            F2 sc = mul2(rr[k], rcp2(add2(s, EPS2)));
            A[3*k]   = mul2(A[3*k],   sc);
            A[3*k+1] = mul2(A[3*k+1], sc);
            A[3*k+2] = mul2(A[3*k+2], sc);
        }
        #pragma unroll
        for (int k = 0; k < 3; k++){
            F2 s  = add2(add2(A[k], A[k+3]), A[k+6]);
            F2 sc = mul2(cc[k], rcp2(add2(s, EPS2)));
            A[k]   = mul2(A[k],   sc);
            A[k+3] = mul2(A[k+3], sc);
            A[k+6] = mul2(A[k+6], sc);
        }
    }

    // ---- Assemble mus (4x4 per row) + V ----
    // mum0 = M - r (third component exactly 0); mu0f = F - c (third exactly 0).
    {
        float m0 = f2lo(mm[0]) - f2lo(rr[0]);
        float m1 = f2lo(mm[1]) - f2lo(rr[1]);
        float f0 = f2lo(mm[3]) - f2lo(cc[0]);
        float f1 = f2lo(mm[4]) - f2lo(cc[1]);
        float4* o = (float4*)(out + r0 * 16);
        o[0] = make_float4(f2lo(A[0]), f2lo(A[1]), f2lo(A[2]), m0);
        o[1] = make_float4(f2lo(A[3]), f2lo(A[4]), f2lo(A[5]), m1);
        o[2] = make_float4(f2lo(A[6]), f2lo(A[7]), f2lo(A[8]), 0.f);
        o[3] = make_float4(f0, f1, 0.f, 0.f);
        long long vidx = (long long)Btot * 16 + r0;
        if (vidx < outsz) out[vidx] = f2lo(Vv);
    }
    if (hasHi){
        float m0 = f2hi(mm[0]) - f2hi(rr[0]);
        float m1 = f2hi(mm[1]) - f2hi(rr[1]);
        float f0 = f2hi(mm[3]) - f2hi(cc[0]);
        float f1 = f2hi(mm[4]) - f2hi(cc[1]);
        float4* o = (float4*)(out + r1 * 16);
        o[0] = make_float4(f2hi(A[0]), f2hi(A[1]), f2hi(A[2]), m0);
        o[1] = make_float4(f2hi(A[3]), f2hi(A[4]), f2hi(A[5]), m1);
        o[2] = make_float4(f2hi(A[6]), f2hi(A[7]), f2hi(A[8]), 0.f);
        o[3] = make_float4(f0, f1, 0.f, 0.f);
        long long vidx = (long long)Btot * 16 + r1;
        if (vidx < outsz) out[vidx] = f2hi(Vv);
    }
}

extern "C" void kernel_launch(void* const* d_in, const int* in_sizes, int n_in,
                              void* d_out, int out_size)
{
    const float* margins = (const float*)d_in[0];
    const float* W1 = (const float*)d_in[1];
    const float* b1 = (const float*)d_in[2];
    const float* W2 = (const float*)d_in[3];
    const float* b2 = (const float*)d_in[4];
    const float* W3 = (const float*)d_in[5];
    const float* b3 = (const float*)d_in[6];
    float* out = (float*)d_out;

    const int B = in_sizes[0] / 8;
    const int nthreads = (B + 1) / 2;
    const int block = 128;
    const int grid = (nthreads + block - 1) / block;
    (void)n_in;
    sinkhornm_kernel<<<grid, block>>>(margins, W1, b1, W2, b2, W3, b3,
                                      out, B, (long long)out_size);
}

// round 2
// speedup vs baseline: 1.2679x; 1.2679x over previous
#include <cuda_runtime.h>

// SinkhornM: per-row MLP (8->32->16->9) -> tau -> sigmoid shares -> 10-iter
// Sinkhorn (u/v form) -> assemble 4x4 mus + V.
// Neuron-SIMD f32x2: each F2 holds two adjacent OUTPUT neurons of one row, so
// raw row-major weights are loaded as ready-made f32x2 operands (no dup).
// Two rows per thread amortize every weight LDS across two fma2's.

typedef unsigned long long F2;

static __device__ __forceinline__ float f2lo(F2 v){ return __uint_as_float((unsigned)v); }
static __device__ __forceinline__ float f2hi(F2 v){ return __uint_as_float((unsigned)(v >> 32)); }
static __device__ __forceinline__ F2 mkf2(float lo, float hi){
    return (F2)__float_as_uint(lo) | ((F2)__float_as_uint(hi) << 32);
}
static __device__ __forceinline__ F2 bb(float v){ return mkf2(v, v); }

static __device__ __forceinline__ F2 fma2(F2 a, F2 b, F2 c){
    F2 d; asm("fma.rn.f32x2 %0, %1, %2, %3;" : "=l"(d) : "l"(a), "l"(b), "l"(c)); return d;
}
static __device__ __forceinline__ F2 mul2(F2 a, F2 b){
    F2 d; asm("mul.rn.f32x2 %0, %1, %2;" : "=l"(d) : "l"(a), "l"(b)); return d;
}
static __device__ __forceinline__ F2 add2(F2 a, F2 b){
    F2 d; asm("add.rn.f32x2 %0, %1, %2;" : "=l"(d) : "l"(a), "l"(b)); return d;
}
static __device__ __forceinline__ float rcpa(float x){ float r; asm("rcp.approx.ftz.f32 %0, %1;" : "=f"(r) : "f"(x)); return r; }
static __device__ __forceinline__ float sqrta(float x){ float r; asm("sqrt.approx.ftz.f32 %0, %1;" : "=f"(r) : "f"(x)); return r; }
static __device__ __forceinline__ float ex2a(float x){ float r; asm("ex2.approx.ftz.f32 %0, %1;" : "=f"(r) : "f"(x)); return r; }

static __device__ __forceinline__ F2 rcp2(F2 v){ return mkf2(rcpa(f2lo(v)), rcpa(f2hi(v))); }
static __device__ __forceinline__ F2 sqrt2(F2 v){ return mkf2(sqrta(f2lo(v)), sqrta(f2hi(v))); }
static __device__ __forceinline__ F2 ex2_2(F2 v){ return mkf2(ex2a(f2lo(v)), ex2a(f2hi(v))); }
static __device__ __forceinline__ F2 dupf(float v){ return mkf2(v, v); }

__global__ __launch_bounds__(128, 4)
void sinkhornm_kernel(const float* __restrict__ margins,
                      const float* __restrict__ W1, const float* __restrict__ b1,
                      const float* __restrict__ W2, const float* __restrict__ b2,
                      const float* __restrict__ W3, const float* __restrict__ b3,
                      float* __restrict__ out, int Btot, long long outsz)
{
    // Raw (non-duplicated) weights, float4-aligned.
    __shared__ __align__(16) float sW1[256];   // [8][32]
    __shared__ __align__(16) float sB1[32];
    __shared__ __align__(16) float sW2[512];   // [32][16]
    __shared__ __align__(16) float sB2[16];
    __shared__ __align__(16) float sW3[192];   // [16][12], cols 9..11 = 0
    __shared__ __align__(16) float sB3[12];    // 9 real + 3 zero

    const int tid = threadIdx.x;
    for (int i = tid; i < 256; i += blockDim.x) sW1[i] = W1[i];
    for (int i = tid; i < 32;  i += blockDim.x) sB1[i] = b1[i];
    for (int i = tid; i < 512; i += blockDim.x) sW2[i] = W2[i];
    for (int i = tid; i < 16;  i += blockDim.x) sB2[i] = b2[i];
    for (int i = tid; i < 192; i += blockDim.x){
        int r = i / 12, c = i % 12;
        sW3[i] = (c < 9) ? W3[r * 9 + c] : 0.0f;
    }
    for (int i = tid; i < 12;  i += blockDim.x) sB3[i] = (i < 9) ? b3[i] : 0.0f;
    __syncthreads();

    const long long t  = (long long)blockIdx.x * blockDim.x + tid;
    const long long r0 = 2 * t;
    if (r0 >= Btot) return;
    const bool hasHi = (r0 + 1) < Btot;
    const long long r1 = hasHi ? (r0 + 1) : r0;

    // Load margins for two rows; duplicate each scalar into (x,x) for the MLP.
    const float4* mga = (const float4*)(margins + r0 * 8);
    const float4* mgb = (const float4*)(margins + r1 * 8);
    const float4 a0 = mga[0], a1 = mga[1];
    const float4 q0 = mgb[0], q1 = mgb[1];

    F2 xA[8], xB[8];
    xA[0]=dupf(a0.x); xA[1]=dupf(a0.y); xA[2]=dupf(a0.z); xA[3]=dupf(a0.w);
    xA[4]=dupf(a1.x); xA[5]=dupf(a1.y); xA[6]=dupf(a1.z); xA[7]=dupf(a1.w);
    xB[0]=dupf(q0.x); xB[1]=dupf(q0.y); xB[2]=dupf(q0.z); xB[3]=dupf(q0.w);
    xB[4]=dupf(q1.x); xB[5]=dupf(q1.y); xB[6]=dupf(q1.z); xB[7]=dupf(q1.w);

    // ---- Fused layers 1+2: per group of 4 hidden units, accumulate into g ----
    F2 gA[8], gB[8];  // 16 layer-2 outputs as 8 neuron-pairs per row
    {
        const float4* bv = (const float4*)sB2;
        #pragma unroll
        for (int j = 0; j < 4; j++){
            float4 b = bv[j];
            F2 w01 = mkf2(b.x, b.y), w23 = mkf2(b.z, b.w);
            gA[2*j] = w01; gA[2*j+1] = w23;
            gB[2*j] = w01; gB[2*j+1] = w23;
        }
    }
    const float4* W1v = (const float4*)sW1;
    const float4* W2v = (const float4*)sW2;
    const float4* B1v = (const float4*)sB1;
    #pragma unroll
    for (int q = 0; q < 8; q++){
        float4 b = B1v[q];
        F2 h0A = mkf2(b.x, b.y), h1A = mkf2(b.z, b.w);
        F2 h0B = h0A, h1B = h1A;
        #pragma unroll
        for (int k = 0; k < 8; k++){
            float4 w = W1v[k*8 + q];
            F2 w01 = mkf2(w.x, w.y), w23 = mkf2(w.z, w.w);
            h0A = fma2(xA[k], w01, h0A); h1A = fma2(xA[k], w23, h1A);
            h0B = fma2(xB[k], w01, h0B); h1B = fma2(xB[k], w23, h1B);
        }
        float hA0 = fmaxf(f2lo(h0A), 0.f), hA1 = fmaxf(f2hi(h0A), 0.f);
        float hA2 = fmaxf(f2lo(h1A), 0.f), hA3 = fmaxf(f2hi(h1A), 0.f);
        float hB0 = fmaxf(f2lo(h0B), 0.f), hB1 = fmaxf(f2hi(h0B), 0.f);
        float hB2 = fmaxf(f2lo(h1B), 0.f), hB3 = fmaxf(f2hi(h1B), 0.f);
        float hAs[4] = {hA0, hA1, hA2, hA3};
        float hBs[4] = {hB0, hB1, hB2, hB3};
        #pragma unroll
        for (int s = 0; s < 4; s++){
            const int k2 = 4*q + s;
            F2 ya = dupf(hAs[s]), yb = dupf(hBs[s]);
            #pragma unroll
            for (int j = 0; j < 4; j++){
                float4 w = W2v[k2*4 + j];
                F2 w01 = mkf2(w.x, w.y), w23 = mkf2(w.z, w.w);
                gA[2*j]   = fma2(ya, w01, gA[2*j]);
                gA[2*j+1] = fma2(ya, w23, gA[2*j+1]);
                gB[2*j]   = fma2(yb, w01, gB[2*j]);
                gB[2*j+1] = fma2(yb, w23, gB[2*j+1]);
            }
        }
    }

    // Row-packed margins (A_k, B_k) for later stages; x regs die after this.
    F2 mP[6];
    #pragma unroll
    for (int k = 0; k < 6; k++) mP[k] = mkf2(f2lo(xA[k]), f2lo(xB[k]));

    // ---- Layer 3: 16 -> 9 (padded to 10 via (p8, 0) pair) ----
    F2 P0A, P1A, P2A, P3A, P4A, P0B, P1B, P2B, P3B, P4B;
    {
        const float4* bv = (const float4*)sB3;
        float4 c0 = bv[0], c1 = bv[1];
        F2 b8 = ((const F2*)sB3)[4];
        P0A = mkf2(c0.x, c0.y); P1A = mkf2(c0.z, c0.w);
        P2A = mkf2(c1.x, c1.y); P3A = mkf2(c1.z, c1.w);
        P4A = b8;
        P0B = P0A; P1B = P1A; P2B = P2A; P3B = P3A; P4B = P4A;
    }
    #pragma unroll
    for (int k = 0; k < 16; k++){
        float va = fmaxf((k & 1) ? f2hi(gA[k >> 1]) : f2lo(gA[k >> 1]), 0.f);
        float vb = fmaxf((k & 1) ? f2hi(gB[k >> 1]) : f2lo(gB[k >> 1]), 0.f);
        F2 ya = dupf(va), yb = dupf(vb);
        const float* wr = sW3 + k*12;
        float4 w0 = *(const float4*)(wr);
        float4 w1 = *(const float4*)(wr + 4);
        F2 w8 = *(const F2*)(wr + 8);
        F2 w01 = mkf2(w0.x, w0.y), w23 = mkf2(w0.z, w0.w);
        F2 w45 = mkf2(w1.x, w1.y), w67 = mkf2(w1.z, w1.w);
        P0A = fma2(ya, w01, P0A); P1A = fma2(ya, w23, P1A);
        P2A = fma2(ya, w45, P2A); P3A = fma2(ya, w67, P3A);
        P4A = fma2(ya, w8,  P4A);
        P0B = fma2(yb, w01, P0B); P1B = fma2(yb, w23, P1B);
        P2B = fma2(yb, w45, P2B); P3B = fma2(yb, w67, P3B);
        P4B = fma2(yb, w8,  P4B);
    }

    // Repack p to row-SIMD: p_i = (rowA_i, rowB_i)
    F2 p0 = mkf2(f2lo(P0A), f2lo(P0B)), p1 = mkf2(f2hi(P0A), f2hi(P0B));
    F2 p2 = mkf2(f2lo(P1A), f2lo(P1B)), p3 = mkf2(f2hi(P1A), f2hi(P1B));
    F2 p4 = mkf2(f2lo(P2A), f2lo(P2B)), p5 = mkf2(f2hi(P2A), f2hi(P2B));
    F2 p6 = mkf2(f2lo(P3A), f2lo(P3B)), p7 = mkf2(f2hi(P3A), f2hi(P3B));
    F2 p8 = mkf2(f2lo(P4A), f2lo(P4B));

    // ---- tau via half-exponents: G_i = exp(p_i / 2) ----
    const F2 HL2E = bb(0.72134752044448170f);  // log2(e)/2
    F2 G0 = ex2_2(mul2(p0, HL2E));
    F2 G1 = ex2_2(mul2(p1, HL2E));
    F2 G2 = ex2_2(mul2(p2, HL2E));
    F2 G3 = ex2_2(mul2(p3, HL2E));
    F2 A0 = mul2(G0, G0), A1 = mul2(G1, G1), A2 = mul2(G0, G1);
    F2 A3 = mul2(G2, G2), A4 = mul2(G3, G3), A5 = mul2(G2, G3);
    F2 A6 = mul2(G0, G2), A7 = mul2(G1, G3);
    F2 A8 = sqrt2(mul2(A6, A7));

    // ---- sqs(x) = 0.02 + 0.96*sigmoid(x); V = exp(p8) ----
    const F2 NL2E = bb(-1.4426950408889634f);
    const F2 L2E  = bb( 1.4426950408889634f);
    const F2 ONE  = bb(1.0f);
    const F2 C96  = bb(0.96f);
    const F2 C02  = bb(0.02f);
    F2 sm0 = fma2(rcp2(add2(ex2_2(mul2(p4, NL2E)), ONE)), C96, C02);
    F2 sm1 = fma2(rcp2(add2(ex2_2(mul2(p5, NL2E)), ONE)), C96, C02);
    F2 sf0 = fma2(rcp2(add2(ex2_2(mul2(p6, NL2E)), ONE)), C96, C02);
    F2 sf1 = fma2(rcp2(add2(ex2_2(mul2(p7, NL2E)), ONE)), C96, C02);
    F2 Vv  = ex2_2(mul2(p8, L2E));

    // Margins: rr = M*shm, cc = F*shf (third components are M2/F2 themselves)
    F2 rr0 = mul2(mP[0], sm0), rr1 = mul2(mP[1], sm1), rr2 = mP[2];
    F2 cc0 = mul2(mP[3], sf0), cc1 = mul2(mP[4], sf1), cc2 = mP[5];

    // ---- Sinkhorn in u/v form (A0 fixed), eps dropped (<1e-11 effect) ----
    F2 u0, u1, u2, v0, v1, v2;
    {   // iteration 0: v = 1 -> row sums are plain adds
        F2 t0 = add2(add2(A0, A1), A2); u0 = mul2(rr0, rcp2(t0));
        F2 t1 = add2(add2(A3, A4), A5); u1 = mul2(rr1, rcp2(t1));
        F2 t2 = add2(add2(A6, A7), A8); u2 = mul2(rr2, rcp2(t2));
        F2 s0 = fma2(A6, u2, fma2(A3, u1, mul2(A0, u0))); v0 = mul2(cc0, rcp2(s0));
        F2 s1 = fma2(A7, u2, fma2(A4, u1, mul2(A1, u0))); v1 = mul2(cc1, rcp2(s1));
        F2 s2 = fma2(A8, u2, fma2(A5, u1, mul2(A2, u0))); v2 = mul2(cc2, rcp2(s2));
    }
    #pragma unroll 1
    for (int it = 1; it < 10; it++){
        F2 t0 = fma2(A2, v2, fma2(A1, v1, mul2(A0, v0))); u0 = mul2(rr0, rcp2(t0));
        F2 t1 = fma2(A5, v2, fma2(A4, v1, mul2(A3, v0))); u1 = mul2(rr1, rcp2(t1));
        F2 t2 = fma2(A8, v2, fma2(A7, v1, mul2(A6, v0))); u2 = mul2(rr2, rcp2(t2));
        F2 s0 = fma2(A6, u2, fma2(A3, u1, mul2(A0, u0))); v0 = mul2(cc0, rcp2(s0));
        F2 s1 = fma2(A7, u2, fma2(A4, u1, mul2(A1, u0))); v1 = mul2(cc1, rcp2(s1));
        F2 s2 = fma2(A8, u2, fma2(A5, u1, mul2(A2, u0))); v2 = mul2(cc2, rcp2(s2));
    }

    // Materialize final A = diag(u) A0 diag(v)
    A0 = mul2(mul2(A0, u0), v0); A1 = mul2(mul2(A1, u0), v1); A2 = mul2(mul2(A2, u0), v2);
    A3 = mul2(mul2(A3, u1), v0); A4 = mul2(mul2(A4, u1), v1); A5 = mul2(mul2(A5, u1), v2);
    A6 = mul2(mul2(A6, u2), v0); A7 = mul2(mul2(A7, u2), v1); A8 = mul2(mul2(A8, u2), v2);

    // ---- Assemble 4x4 mus + V ----
    {
        float m0 = f2lo(mP[0]) - f2lo(rr0);
        float m1 = f2lo(mP[1]) - f2lo(rr1);
        float f0 = f2lo(mP[3]) - f2lo(cc0);
        float f1 = f2lo(mP[4]) - f2lo(cc1);
        float4* o = (float4*)(out + r0 * 16);
        o[0] = make_float4(f2lo(A0), f2lo(A1), f2lo(A2), m0);
        o[1] = make_float4(f2lo(A3), f2lo(A4), f2lo(A5), m1);
        o[2] = make_float4(f2lo(A6), f2lo(A7), f2lo(A8), 0.f);
        o[3] = make_float4(f0, f1, 0.f, 0.f);
        long long vidx = (long long)Btot * 16 + r0;
        if (vidx < outsz) out[vidx] = f2lo(Vv);
    }
    if (hasHi){
        float m0 = f2hi(mP[0]) - f2hi(rr0);
        float m1 = f2hi(mP[1]) - f2hi(rr1);
        float f0 = f2hi(mP[3]) - f2hi(cc0);
        float f1 = f2hi(mP[4]) - f2hi(cc1);
        float4* o = (float4*)(out + r1 * 16);
        o[0] = make_float4(f2hi(A0), f2hi(A1), f2hi(A2), m0);
        o[1] = make_float4(f2hi(A3), f2hi(A4), f2hi(A5), m1);
        o[2] = make_float4(f2hi(A6), f2hi(A7), f2hi(A8), 0.f);
        o[3] = make_float4(f0, f1, 0.f, 0.f);
        long long vidx = (long long)Btot * 16 + r1;
        if (vidx < outsz) out[vidx] = f2hi(Vv);
    }
}

extern "C" void kernel_launch(void* const* d_in, const int* in_sizes, int n_in,
                              void* d_out, int out_size)
{
    const float* margins = (const float*)d_in[0];
    const float* W1 = (const float*)d_in[1];
    const float* b1 = (const float*)d_in[2];
    const float* W2 = (const float*)d_in[3];
    const float* b2 = (const float*)d_in[4];
    const float* W3 = (const float*)d_in[5];
    const float* b3 = (const float*)d_in[6];
    float* out = (float*)d_out;

    const int B = in_sizes[0] / 8;
    const int nthreads = (B + 1) / 2;
    const int block = 128;
    const int grid = (nthreads + block - 1) / block;
    (void)n_in;
    sinkhornm_kernel<<<grid, block>>>(margins, W1, b1, W2, b2, W3, b3,
                                      out, B, (long long)out_size);
}

// round 3
// speedup vs baseline: 1.2761x; 1.0064x over previous
#include <cuda_runtime.h>

// SinkhornM: per-row MLP (8->32->16->9) -> tau -> sigmoid shares -> 10-iter
// Sinkhorn (u/v form) -> assemble 4x4 mus + V.
// Neuron-SIMD f32x2, two rows per thread. Weights live in __constant__ memory
// (copied via D2D cudaMemcpyToSymbolAsync in kernel_launch): weight reads go
// through the constant port (LDC/LDCU) instead of the shared/L1 crossbar,
// which was the binding pipe (62.8% L1) in the previous round.

typedef unsigned long long F2;

__constant__ float cW1[256];   // [8][32] row-major
__constant__ float cB1[32];
__constant__ float cW2[512];   // [32][16] row-major
__constant__ float cB2[16];
__constant__ float cW3[192];   // [16][12], cols 9..11 stay zero (padding)
__constant__ float cB3[12];    // 9 real + 3 zero

static __device__ __forceinline__ float f2lo(F2 v){ return __uint_as_float((unsigned)v); }
static __device__ __forceinline__ float f2hi(F2 v){ return __uint_as_float((unsigned)(v >> 32)); }
static __device__ __forceinline__ F2 mkf2(float lo, float hi){
    return (F2)__float_as_uint(lo) | ((F2)__float_as_uint(hi) << 32);
}
static __device__ __forceinline__ F2 bb(float v){ return mkf2(v, v); }

static __device__ __forceinline__ F2 fma2(F2 a, F2 b, F2 c){
    F2 d; asm("fma.rn.f32x2 %0, %1, %2, %3;" : "=l"(d) : "l"(a), "l"(b), "l"(c)); return d;
}
static __device__ __forceinline__ F2 mul2(F2 a, F2 b){
    F2 d; asm("mul.rn.f32x2 %0, %1, %2;" : "=l"(d) : "l"(a), "l"(b)); return d;
}
static __device__ __forceinline__ F2 add2(F2 a, F2 b){
    F2 d; asm("add.rn.f32x2 %0, %1, %2;" : "=l"(d) : "l"(a), "l"(b)); return d;
}
static __device__ __forceinline__ float rcpa(float x){ float r; asm("rcp.approx.ftz.f32 %0, %1;" : "=f"(r) : "f"(x)); return r; }
static __device__ __forceinline__ float sqrta(float x){ float r; asm("sqrt.approx.ftz.f32 %0, %1;" : "=f"(r) : "f"(x)); return r; }
static __device__ __forceinline__ float ex2a(float x){ float r; asm("ex2.approx.ftz.f32 %0, %1;" : "=f"(r) : "f"(x)); return r; }

static __device__ __forceinline__ F2 rcp2(F2 v){ return mkf2(rcpa(f2lo(v)), rcpa(f2hi(v))); }
static __device__ __forceinline__ F2 sqrt2(F2 v){ return mkf2(sqrta(f2lo(v)), sqrta(f2hi(v))); }
static __device__ __forceinline__ F2 ex2_2(F2 v){ return mkf2(ex2a(f2lo(v)), ex2a(f2hi(v))); }
static __device__ __forceinline__ F2 dupf(float v){ return mkf2(v, v); }

__global__ __launch_bounds__(128, 5)
void sinkhornm_kernel(const float* __restrict__ margins,
                      float* __restrict__ out, int Btot, long long outsz)
{
    const int tid = threadIdx.x;
    const long long t  = (long long)blockIdx.x * blockDim.x + tid;
    const long long r0 = 2 * t;
    if (r0 >= Btot) return;
    const bool hasHi = (r0 + 1) < Btot;
    const long long r1 = hasHi ? (r0 + 1) : r0;

    // Load margins for two rows; duplicate each scalar into (x,x) for the MLP.
    const float4* mga = (const float4*)(margins + r0 * 8);
    const float4* mgb = (const float4*)(margins + r1 * 8);
    const float4 a0 = mga[0], a1 = mga[1];
    const float4 q0 = mgb[0], q1 = mgb[1];

    F2 xA[8], xB[8];
    xA[0]=dupf(a0.x); xA[1]=dupf(a0.y); xA[2]=dupf(a0.z); xA[3]=dupf(a0.w);
    xA[4]=dupf(a1.x); xA[5]=dupf(a1.y); xA[6]=dupf(a1.z); xA[7]=dupf(a1.w);
    xB[0]=dupf(q0.x); xB[1]=dupf(q0.y); xB[2]=dupf(q0.z); xB[3]=dupf(q0.w);
    xB[4]=dupf(q1.x); xB[5]=dupf(q1.y); xB[6]=dupf(q1.z); xB[7]=dupf(q1.w);

    // ---- Fused layers 1+2: per group of 4 hidden units, accumulate into g ----
    F2 gA[8], gB[8];  // 16 layer-2 outputs as 8 neuron-pairs per row
    {
        #pragma unroll
        for (int j = 0; j < 4; j++){
            float4 b = *(const float4*)(cB2 + 4*j);
            F2 w01 = mkf2(b.x, b.y), w23 = mkf2(b.z, b.w);
            gA[2*j] = w01; gA[2*j+1] = w23;
            gB[2*j] = w01; gB[2*j+1] = w23;
        }
    }
    #pragma unroll
    for (int q = 0; q < 8; q++){
        float4 b = *(const float4*)(cB1 + 4*q);
        F2 h0A = mkf2(b.x, b.y), h1A = mkf2(b.z, b.w);
        F2 h0B = h0A, h1B = h1A;
        #pragma unroll
        for (int k = 0; k < 8; k++){
            float4 w = *(const float4*)(cW1 + (k*8 + q)*4);
            F2 w01 = mkf2(w.x, w.y), w23 = mkf2(w.z, w.w);
            h0A = fma2(xA[k], w01, h0A); h1A = fma2(xA[k], w23, h1A);
            h0B = fma2(xB[k], w01, h0B); h1B = fma2(xB[k], w23, h1B);
        }
        float hAs[4] = { fmaxf(f2lo(h0A), 0.f), fmaxf(f2hi(h0A), 0.f),
                         fmaxf(f2lo(h1A), 0.f), fmaxf(f2hi(h1A), 0.f) };
        float hBs[4] = { fmaxf(f2lo(h0B), 0.f), fmaxf(f2hi(h0B), 0.f),
                         fmaxf(f2lo(h1B), 0.f), fmaxf(f2hi(h1B), 0.f) };
        #pragma unroll
        for (int s = 0; s < 4; s++){
            const int k2 = 4*q + s;
            F2 ya = dupf(hAs[s]), yb = dupf(hBs[s]);
            #pragma unroll
            for (int j = 0; j < 4; j++){
                float4 w = *(const float4*)(cW2 + (k2*4 + j)*4);
                F2 w01 = mkf2(w.x, w.y), w23 = mkf2(w.z, w.w);
                gA[2*j]   = fma2(ya, w01, gA[2*j]);
                gA[2*j+1] = fma2(ya, w23, gA[2*j+1]);
                gB[2*j]   = fma2(yb, w01, gB[2*j]);
                gB[2*j+1] = fma2(yb, w23, gB[2*j+1]);
            }
        }
    }

    // Row-packed margins (A_k, B_k) for later stages; x regs die after this.
    F2 mP[6];
    #pragma unroll
    for (int k = 0; k < 6; k++) mP[k] = mkf2(f2lo(xA[k]), f2lo(xB[k]));

    // ---- Layer 3: 16 -> 9 (padded to 10 via (p8, 0) pair) ----
    F2 P0A, P1A, P2A, P3A, P4A, P0B, P1B, P2B, P3B, P4B;
    {
        float4 c0 = *(const float4*)(cB3);
        float4 c1 = *(const float4*)(cB3 + 4);
        F2 b8 = *(const F2*)(cB3 + 8);
        P0A = mkf2(c0.x, c0.y); P1A = mkf2(c0.z, c0.w);
        P2A = mkf2(c1.x, c1.y); P3A = mkf2(c1.z, c1.w);
        P4A = b8;
        P0B = P0A; P1B = P1A; P2B = P2A; P3B = P3A; P4B = P4A;
    }
    #pragma unroll
    for (int k = 0; k < 16; k++){
        float va = fmaxf((k & 1) ? f2hi(gA[k >> 1]) : f2lo(gA[k >> 1]), 0.f);
        float vb = fmaxf((k & 1) ? f2hi(gB[k >> 1]) : f2lo(gB[k >> 1]), 0.f);
        F2 ya = dupf(va), yb = dupf(vb);
        float4 w0 = *(const float4*)(cW3 + k*12);
        float4 w1 = *(const float4*)(cW3 + k*12 + 4);
        F2 w8 = *(const F2*)(cW3 + k*12 + 8);
        F2 w01 = mkf2(w0.x, w0.y), w23 = mkf2(w0.z, w0.w);
        F2 w45 = mkf2(w1.x, w1.y), w67 = mkf2(w1.z, w1.w);
        P0A = fma2(ya, w01, P0A); P1A = fma2(ya, w23, P1A);
        P2A = fma2(ya, w45, P2A); P3A = fma2(ya, w67, P3A);
        P4A = fma2(ya, w8,  P4A);
        P0B = fma2(yb, w01, P0B); P1B = fma2(yb, w23, P1B);
        P2B = fma2(yb, w45, P2B); P3B = fma2(yb, w67, P3B);
        P4B = fma2(yb, w8,  P4B);
    }

    // Repack p to row-SIMD: p_i = (rowA_i, rowB_i)
    F2 p0 = mkf2(f2lo(P0A), f2lo(P0B)), p1 = mkf2(f2hi(P0A), f2hi(P0B));
    F2 p2 = mkf2(f2lo(P1A), f2lo(P1B)), p3 = mkf2(f2hi(P1A), f2hi(P1B));
    F2 p4 = mkf2(f2lo(P2A), f2lo(P2B)), p5 = mkf2(f2hi(P2A), f2hi(P2B));
    F2 p6 = mkf2(f2lo(P3A), f2lo(P3B)), p7 = mkf2(f2hi(P3A), f2hi(P3B));
    F2 p8 = mkf2(f2lo(P4A), f2lo(P4B));

    // ---- tau via half-exponents: G_i = exp(p_i / 2) ----
    const F2 HL2E = bb(0.72134752044448170f);  // log2(e)/2
    F2 G0 = ex2_2(mul2(p0, HL2E));
    F2 G1 = ex2_2(mul2(p1, HL2E));
    F2 G2 = ex2_2(mul2(p2, HL2E));
    F2 G3 = ex2_2(mul2(p3, HL2E));
    F2 A0 = mul2(G0, G0), A1 = mul2(G1, G1), A2 = mul2(G0, G1);
    F2 A3 = mul2(G2, G2), A4 = mul2(G3, G3), A5 = mul2(G2, G3);
    F2 A6 = mul2(G0, G2), A7 = mul2(G1, G3);
    F2 A8 = sqrt2(mul2(A6, A7));

    // ---- sqs(x) = 0.02 + 0.96*sigmoid(x); V = exp(p8) ----
    const F2 NL2E = bb(-1.4426950408889634f);
    const F2 L2E  = bb( 1.4426950408889634f);
    const F2 ONE  = bb(1.0f);
    const F2 C96  = bb(0.96f);
    const F2 C02  = bb(0.02f);
    F2 sm0 = fma2(rcp2(add2(ex2_2(mul2(p4, NL2E)), ONE)), C96, C02);
    F2 sm1 = fma2(rcp2(add2(ex2_2(mul2(p5, NL2E)), ONE)), C96, C02);
    F2 sf0 = fma2(rcp2(add2(ex2_2(mul2(p6, NL2E)), ONE)), C96, C02);
    F2 sf1 = fma2(rcp2(add2(ex2_2(mul2(p7, NL2E)), ONE)), C96, C02);
    F2 Vv  = ex2_2(mul2(p8, L2E));

    // Margins: rr = M*shm, cc = F*shf (third components are M2/F2 themselves)
    F2 rr0 = mul2(mP[0], sm0), rr1 = mul2(mP[1], sm1), rr2 = mP[2];
    F2 cc0 = mul2(mP[3], sf0), cc1 = mul2(mP[4], sf1), cc2 = mP[5];

    // ---- Sinkhorn in u/v form (A fixed), eps dropped (<1e-11 effect) ----
    F2 u0, u1, u2, v0, v1, v2;
    {   // iteration 0: v = 1 -> row sums are plain adds
        F2 t0 = add2(add2(A0, A1), A2); u0 = mul2(rr0, rcp2(t0));
        F2 t1 = add2(add2(A3, A4), A5); u1 = mul2(rr1, rcp2(t1));
        F2 t2 = add2(add2(A6, A7), A8); u2 = mul2(rr2, rcp2(t2));
        F2 s0 = fma2(A6, u2, fma2(A3, u1, mul2(A0, u0))); v0 = mul2(cc0, rcp2(s0));
        F2 s1 = fma2(A7, u2, fma2(A4, u1, mul2(A1, u0))); v1 = mul2(cc1, rcp2(s1));
        F2 s2 = fma2(A8, u2, fma2(A5, u1, mul2(A2, u0))); v2 = mul2(cc2, rcp2(s2));
    }
    #pragma unroll 1
    for (int it = 1; it < 10; it++){
        F2 t0 = fma2(A2, v2, fma2(A1, v1, mul2(A0, v0))); u0 = mul2(rr0, rcp2(t0));
        F2 t1 = fma2(A5, v2, fma2(A4, v1, mul2(A3, v0))); u1 = mul2(rr1, rcp2(t1));
        F2 t2 = fma2(A8, v2, fma2(A7, v1, mul2(A6, v0))); u2 = mul2(rr2, rcp2(t2));
        F2 s0 = fma2(A6, u2, fma2(A3, u1, mul2(A0, u0))); v0 = mul2(cc0, rcp2(s0));
        F2 s1 = fma2(A7, u2, fma2(A4, u1, mul2(A1, u0))); v1 = mul2(cc1, rcp2(s1));
        F2 s2 = fma2(A8, u2, fma2(A5, u1, mul2(A2, u0))); v2 = mul2(cc2, rcp2(s2));
    }

    // Materialize final A = diag(u) A diag(v)
    A0 = mul2(mul2(A0, u0), v0); A1 = mul2(mul2(A1, u0), v1); A2 = mul2(mul2(A2, u0), v2);
    A3 = mul2(mul2(A3, u1), v0); A4 = mul2(mul2(A4, u1), v1); A5 = mul2(mul2(A5, u1), v2);
    A6 = mul2(mul2(A6, u2), v0); A7 = mul2(mul2(A7, u2), v1); A8 = mul2(mul2(A8, u2), v2);

    // ---- Assemble 4x4 mus + V ----
    {
        float m0 = f2lo(mP[0]) - f2lo(rr0);
        float m1 = f2lo(mP[1]) - f2lo(rr1);
        float f0 = f2lo(mP[3]) - f2lo(cc0);
        float f1 = f2lo(mP[4]) - f2lo(cc1);
        float4* o = (float4*)(out + r0 * 16);
        o[0] = make_float4(f2lo(A0), f2lo(A1), f2lo(A2), m0);
        o[1] = make_float4(f2lo(A3), f2lo(A4), f2lo(A5), m1);
        o[2] = make_float4(f2lo(A6), f2lo(A7), f2lo(A8), 0.f);
        o[3] = make_float4(f0, f1, 0.f, 0.f);
        long long vidx = (long long)Btot * 16 + r0;
        if (vidx < outsz) out[vidx] = f2lo(Vv);
    }
    if (hasHi){
        float m0 = f2hi(mP[0]) - f2hi(rr0);
        float m1 = f2hi(mP[1]) - f2hi(rr1);
        float f0 = f2hi(mP[3]) - f2hi(cc0);
        float f1 = f2hi(mP[4]) - f2hi(cc1);
        float4* o = (float4*)(out + r1 * 16);
        o[0] = make_float4(f2hi(A0), f2hi(A1), f2hi(A2), m0);
        o[1] = make_float4(f2hi(A3), f2hi(A4), f2hi(A5), m1);
        o[2] = make_float4(f2hi(A6), f2hi(A7), f2hi(A8), 0.f);
        o[3] = make_float4(f0, f1, 0.f, 0.f);
        long long vidx = (long long)Btot * 16 + r1;
        if (vidx < outsz) out[vidx] = f2hi(Vv);
    }
}

extern "C" void kernel_launch(void* const* d_in, const int* in_sizes, int n_in,
                              void* d_out, int out_size)
{
    const float* margins = (const float*)d_in[0];
    const float* W1 = (const float*)d_in[1];
    const float* b1 = (const float*)d_in[2];
    const float* W2 = (const float*)d_in[3];
    const float* b2 = (const float*)d_in[4];
    const float* W3 = (const float*)d_in[5];
    const float* b3 = (const float*)d_in[6];
    float* out = (float*)d_out;

    // Copy weights into constant memory (device-to-device async memcpys:
    // graph-capturable, no allocation). W3 is copied row-by-row to pad the
    // row stride from 9 to 12 floats for aligned float4/F2 constant loads;
    // pad entries keep their zero-initialized values.
    cudaMemcpyToSymbolAsync(cW1, W1, 256 * sizeof(float), 0, cudaMemcpyDeviceToDevice);
    cudaMemcpyToSymbolAsync(cB1, b1,  32 * sizeof(float), 0, cudaMemcpyDeviceToDevice);
    cudaMemcpyToSymbolAsync(cW2, W2, 512 * sizeof(float), 0, cudaMemcpyDeviceToDevice);
    cudaMemcpyToSymbolAsync(cB2, b2,  16 * sizeof(float), 0, cudaMemcpyDeviceToDevice);
    for (int r = 0; r < 16; r++){
        cudaMemcpyToSymbolAsync(cW3, W3 + r * 9, 9 * sizeof(float),
                                r * 12 * sizeof(float), cudaMemcpyDeviceToDevice);
    }
    cudaMemcpyToSymbolAsync(cB3, b3, 9 * sizeof(float), 0, cudaMemcpyDeviceToDevice);

    const int B = in_sizes[0] / 8;
    const int nthreads = (B + 1) / 2;
    const int block = 128;
    const int grid = (nthreads + block - 1) / block;
    (void)n_in;
    sinkhornm_kernel<<<grid, block>>>(margins, out, B, (long long)out_size);
}